// round 16
// baseline (speedup 1.0000x reference)
#include <cuda_runtime.h>
#include <cuda_fp16.h>
#include <cstdint>

#define IH 400
#define IW 400
#define NPIX 160000
#define F1 128
#define F2 64
#define F3 8

#define PW 416                 // padded image stride / height
#define CH (PW * PW)           // per-channel padded elems (even)
#define NSTEP 25               // k-steps: 396 permuted slots (363 real) + pad

// smem: h2 staging + small tables
#define OFF_H2S 0              // 4 warps x 32 px x 65 f32 = 33280 B
#define OFF_B1S 33280
#define OFF_B2S 33792
#define OFF_B3S 34048
#define OFF_W3S 34080
#define OFF_KOF 36128          // 200 ints = 800 B
#define SMEM_BYTES 36928

#define NPADW (3 * CH / 8)     // 64896 thread-groups for image build
#define PAD_BLOCKS ((NPADW + 255) / 256)          // 254
#define PREP_ITEMS (NSTEP * 16 * 32 + 2048)       // 12800 B1 + 2048 W2

// two fp16 images (u16 values), img1 shifted by one pixel; packed as u32 pairs
__device__ uint4 g_x0[3 * CH / 8];
__device__ uint4 g_x1[3 * CH / 8];
// fp16 B fragments, ni-paired for uint4 loads: uint4 index (t*8+q)*32+lane
__device__ uint2 g_B1f[NSTEP * 16 * 32];
__device__ uint2 g_W2f[2048];

// ---------------- helpers ----------------
__device__ __forceinline__ uint32_t cvt2h(float hi_val, float lo_val) {
    uint32_t r;
    asm("cvt.rn.f16x2.f32 %0, %1, %2;" : "=r"(r) : "f"(hi_val), "f"(lo_val));
    return r;
}
__device__ __forceinline__ float lrelu(float t) { return t > 0.f ? t : 0.01f * t; }

#define MMA(d, a, b0_, b1_) \
    asm("mma.sync.aligned.m16n8k16.row.col.f32.f16.f16.f32 " \
        "{%0,%1,%2,%3},{%4,%5,%6,%7},{%8,%9},{%0,%1,%2,%3};" \
        : "+f"((d).x), "+f"((d).y), "+f"((d).z), "+f"((d).w) \
        : "r"((a)[0]), "r"((a)[1]), "r"((a)[2]), "r"((a)[3]), "r"(b0_), "r"(b1_))

// K-permutation: slot s (0..399) -> weight & x-offset.
// pair pi = s>>1: row r = pi/6 (c = r/11, ki = r%11), m = pi%6, kj = 2m + (s&1).
// Valid iff pi < 198 && kj < 11; x pair base offset (u16) = c*CH + ki*PW + 2m.
__device__ __forceinline__ float w1_slot(const float* W1, int s, int n) {
    int pi = s >> 1;
    if (pi >= 198) return 0.f;
    int r = pi / 6, m = pi - 6 * r;
    int kj = 2 * m + (s & 1);
    if (kj >= 11) return 0.f;
    int c = r / 11, ki = r - 11 * c;
    return W1[(c * 121 + ki * 11 + kj) * F1 + n];
}

// ---------------------------------------------------------------------------
// Prep: build both fp16 images + pack W1/W2 fragments
// ---------------------------------------------------------------------------
__global__ void prep_all_k(const float* __restrict__ x,
                           const float* __restrict__ W1,
                           const float* __restrict__ W2)
{
    if (blockIdx.x < PAD_BLOCKS) {
        int b = blockIdx.x * 256 + threadIdx.x;
        if (b >= NPADW) return;
        int ub = b * 8;                       // u16 base index (row-aligned: PW%8==0)
        int c = ub / CH;
        int rem = ub - c * CH;
        int gy = rem / PW, gx0 = rem - gy * PW;
        int sy = gy - 5;
        unsigned short v[9];
        const float* xr = x + (c * IH + sy) * IW;
#pragma unroll
        for (int k = 0; k < 8; k++) {
            float val = 0.f;
            int sx = gx0 + k - 5;
            if ((unsigned)sy < (unsigned)IH && (unsigned)sx < (unsigned)IW)
                val = __ldg(xr + sx);
            v[k] = __half_as_ushort(__float2half_rn(val));
        }
        {   // v[8]: next u16 position
            float val = 0.f;
            int u = ub + 8;
            if (u < 3 * CH) {
                int c8 = u / CH;
                int r8 = u - c8 * CH;
                int gy8 = r8 / PW, gx8 = r8 - gy8 * PW;
                int sy8 = gy8 - 5, sx8 = gx8 - 5;
                if ((unsigned)sy8 < (unsigned)IH && (unsigned)sx8 < (unsigned)IW)
                    val = __ldg(x + (c8 * IH + sy8) * IW + sx8);
            }
            v[8] = __half_as_ushort(__float2half_rn(val));
        }
        uint4 w0, w1v;
        w0.x = (uint32_t)v[0] | ((uint32_t)v[1] << 16);
        w0.y = (uint32_t)v[2] | ((uint32_t)v[3] << 16);
        w0.z = (uint32_t)v[4] | ((uint32_t)v[5] << 16);
        w0.w = (uint32_t)v[6] | ((uint32_t)v[7] << 16);
        w1v.x = (uint32_t)v[1] | ((uint32_t)v[2] << 16);
        w1v.y = (uint32_t)v[3] | ((uint32_t)v[4] << 16);
        w1v.z = (uint32_t)v[5] | ((uint32_t)v[6] << 16);
        w1v.w = (uint32_t)v[7] | ((uint32_t)v[8] << 16);
        g_x0[b] = w0;
        g_x1[b] = w1v;
        return;
    }

    int t = (blockIdx.x - PAD_BLOCKS) * 256 + threadIdx.x;
    if (t >= PREP_ITEMS) return;
    if (t < NSTEP * 16 * 32) {
        int lane = t & 31, ni = (t >> 5) & 15, it = t >> 9;   // it 0..24
        int c = lane & 3, g = lane >> 2;
        int n = ni * 8 + g;
        int s0 = it * 16 + 2 * c;
        int s1 = s0 + 8;
        uint2 o;
        o.x = cvt2h(w1_slot(W1, s0 + 1, n), w1_slot(W1, s0, n));
        o.y = cvt2h(w1_slot(W1, s1 + 1, n), w1_slot(W1, s1, n));
        g_B1f[(((it << 3) + (ni >> 1)) * 32 + lane) * 2 + (ni & 1)] = o;
    } else {
        int t2 = t - NSTEP * 16 * 32;
        int lane = t2 & 31, ni2 = (t2 >> 5) & 7, kt = t2 >> 8;
        int c = lane & 3, g = lane >> 2;
        int n = ni2 * 8 + g;
        int k0 = kt * 16 + 2 * c;
        uint2 o;
        o.x = cvt2h(W2[(k0 + 1) * F2 + n], W2[k0 * F2 + n]);
        o.y = cvt2h(W2[(k0 + 9) * F2 + n], W2[(k0 + 8) * F2 + n]);
        g_W2f[(((kt << 2) + (ni2 >> 1)) * 32 + lane) * 2 + (ni2 & 1)] = o;
    }
}

// ---------------------------------------------------------------------------
// Main: CTA = 128 px, 4 warps x 32 px. A fragments = single LDG.32 each;
// x pipelined at DISTANCE 2 (3 buffers + rotation), B at distance 1.
// ---------------------------------------------------------------------------
__global__ void __launch_bounds__(128) main_k(const float* __restrict__ b1,
                                              const float* __restrict__ b2,
                                              const float* __restrict__ b3,
                                              const float* __restrict__ W3,
                                              float* __restrict__ out)
{
    extern __shared__ char smem[];
    float* sb1 = (float*)(smem + OFF_B1S);
    float* sb2 = (float*)(smem + OFF_B2S);
    float* sb3 = (float*)(smem + OFF_B3S);
    float* sW3 = (float*)(smem + OFF_W3S);
    int*   skof = (int*)(smem + OFF_KOF);

    const int tid = threadIdx.x;
    const int w = tid >> 5;
    const int lane = tid & 31;
    const int c4 = lane & 3, g = lane >> 2;

    if (tid < F1) sb1[tid] = b1[tid];
    if (tid < F2) sb2[tid] = b2[tid];
    if (tid < F3) sb3[tid] = b3[tid];
    for (int i = tid; i < F2 * F3; i += 128) sW3[i] = W3[i];
    for (int i = tid; i < 200; i += 128) {   // pair pi -> u32 x-offset
        int pi = i;
        int off = 0;
        if (pi < 198) {
            int r = pi / 6, m = pi - 6 * r;
            int c = r / 11, ki = r - 11 * c;
            off = (c * CH + ki * PW + 2 * m) >> 1;
        }
        skof[i] = off;
    }
    __syncthreads();   // only block-wide sync

    // 4 per-lane base pointers (mi,rr), parity-resolved once
    const uint32_t* x0 = (const uint32_t*)g_x0;
    const uint32_t* x1 = (const uint32_t*)g_x1;
    const uint32_t* bptr[4];
#pragma unroll
    for (int mi = 0; mi < 2; mi++)
#pragma unroll
        for (int rr = 0; rr < 2; rr++) {
            int p = blockIdx.x * 128 + w * 32 + mi * 16 + rr * 8 + g;
            int py = p / IW;
            int pb = py * PW + (p - py * IW);
            bptr[mi * 2 + rr] = (pb & 1) ? (x1 + ((pb - 1) >> 1))
                                         : (x0 + (pb >> 1));
        }

    auto ldx8 = [&](int t, uint32_t xf[8]) {
        int o0 = skof[t * 8 + c4];
        int o1 = skof[t * 8 + 4 + c4];
        xf[0] = __ldg(bptr[0] + o0);
        xf[1] = __ldg(bptr[1] + o0);
        xf[2] = __ldg(bptr[0] + o1);
        xf[3] = __ldg(bptr[1] + o1);
        xf[4] = __ldg(bptr[2] + o0);
        xf[5] = __ldg(bptr[3] + o0);
        xf[6] = __ldg(bptr[2] + o1);
        xf[7] = __ldg(bptr[3] + o1);
    };
    auto ldb8 = [&](int t, uint4 bf[8]) {
        const uint4* bp = (const uint4*)g_B1f + t * 256 + lane;
#pragma unroll
        for (int q = 0; q < 8; q++) bf[q] = __ldg(bp + q * 32);
    };

    float4 d1[2][16];
#pragma unroll
    for (int mi = 0; mi < 2; mi++)
#pragma unroll
        for (int ni = 0; ni < 16; ni++) d1[mi][ni] = make_float4(0.f, 0.f, 0.f, 0.f);

    auto domma = [&](const uint32_t* xf, const uint4* bf) {
#pragma unroll
        for (int q = 0; q < 8; q++) {
            MMA(d1[0][2 * q],     xf,     bf[q].x, bf[q].y);
            MMA(d1[1][2 * q],     xf + 4, bf[q].x, bf[q].y);
            MMA(d1[0][2 * q + 1], xf,     bf[q].z, bf[q].w);
            MMA(d1[1][2 * q + 1], xf + 4, bf[q].z, bf[q].w);
        }
    };

    // ==== layer 1: 25 k-steps, unroll x2, x at distance 2, B at distance 1 ==
    uint32_t xA[8], xB[8], xC[8];
    uint4 bA[8], bB[8];
    ldx8(0, xA);
    ldx8(1, xB);
    ldb8(0, bA);
    ldb8(1, bB);
#pragma unroll 1
    for (int t = 0; t < 24; t += 2) {
        // enter: xA=x[t], xB=x[t+1], bA=b[t], bB=b[t+1]
        ldx8(t + 2, xC);                       // distance 2: 2 dommas of shadow
        domma(xA, bA);
        {
            int t3 = (t + 3 < NSTEP) ? t + 3 : NSTEP - 1;
            ldx8(t3, xA);                      // x[t+3], 2 dommas of shadow
            ldb8(t + 2, bA);                   // b[t+2], 1 domma of shadow
        }
        domma(xB, bB);
        {
            int t3 = (t + 3 < NSTEP) ? t + 3 : NSTEP - 1;
            ldb8(t3, bB);                      // b[t+3]
        }
        // rotate: xB <- x[t+3] (in xA), xA <- x[t+2] (in xC)
#pragma unroll
        for (int i = 0; i < 8; i++) { xB[i] = xA[i]; xA[i] = xC[i]; }
    }
    domma(xA, bA);            // t = 24

    // ============ layer 2: bias+leaky+fp16 in regs, mma 128->64 ============
    float4 d2[2][8];
#pragma unroll
    for (int mi = 0; mi < 2; mi++)
#pragma unroll
        for (int ni = 0; ni < 8; ni++) d2[mi][ni] = make_float4(0.f, 0.f, 0.f, 0.f);

#pragma unroll
    for (int kt = 0; kt < 8; kt++) {
        uint32_t ah[2][4];
#pragma unroll
        for (int half = 0; half < 2; half++) {
            int ni = 2 * kt + half;
            float2 bb = *(const float2*)&sb1[8 * ni + 2 * c4];
#pragma unroll
            for (int mi = 0; mi < 2; mi++) {
                float4 D = d1[mi][ni];
                ah[mi][half * 2]     = cvt2h(lrelu(D.y + bb.y), lrelu(D.x + bb.x));
                ah[mi][half * 2 + 1] = cvt2h(lrelu(D.w + bb.y), lrelu(D.z + bb.x));
            }
        }
        const uint4* wp = (const uint4*)g_W2f + kt * 128 + lane;
#pragma unroll
        for (int q = 0; q < 4; q++) {
            uint4 ww = __ldg(wp + q * 32);
            MMA(d2[0][2 * q],     ah[0], ww.x, ww.y);
            MMA(d2[1][2 * q],     ah[1], ww.x, ww.y);
            MMA(d2[0][2 * q + 1], ah[0], ww.z, ww.w);
            MMA(d2[1][2 * q + 1], ah[1], ww.z, ww.w);
        }
    }

    // ============ h2 -> padded smem, per-pixel 64->8 + normalize ===========
    float* h2s = (float*)(smem + OFF_H2S) + w * (32 * 65);
#pragma unroll
    for (int ni = 0; ni < 8; ni++) {
        float2 bb = *(const float2*)&sb2[8 * ni + 2 * c4];
        int ch = 8 * ni + 2 * c4;
#pragma unroll
        for (int mi = 0; mi < 2; mi++) {
            float4 D = d2[mi][ni];
            int r0 = 16 * mi + g;
            h2s[r0 * 65 + ch]           = lrelu(D.x + bb.x);
            h2s[r0 * 65 + ch + 1]       = lrelu(D.y + bb.y);
            h2s[(r0 + 8) * 65 + ch]     = lrelu(D.z + bb.x);
            h2s[(r0 + 8) * 65 + ch + 1] = lrelu(D.w + bb.y);
        }
    }
    __syncwarp();

    const float* myrow = h2s + lane * 65;
    float v[F3];
#pragma unroll
    for (int e = 0; e < F3; e++) v[e] = sb3[e];
#pragma unroll 8
    for (int k = 0; k < F2; k++) {
        float hk = myrow[k];
        const float4* wr = (const float4*)&sW3[k * F3];
        float4 w0 = wr[0], w1 = wr[1];
        v[0] += hk * w0.x; v[1] += hk * w0.y; v[2] += hk * w0.z; v[3] += hk * w0.w;
        v[4] += hk * w1.x; v[5] += hk * w1.y; v[6] += hk * w1.z; v[7] += hk * w1.w;
    }
    float ss = 0.f;
#pragma unroll
    for (int e = 0; e < F3; e++) ss += v[e] * v[e];
    float inv = 1.0f / fmaxf(sqrtf(ss), 1e-12f);

    const int p = blockIdx.x * 128 + w * 32 + lane;
    float4* o = (float4*)(out + (size_t)p * F3);
    float4 o0, o1;
    o0.x = v[0] * inv; o0.y = v[1] * inv; o0.z = v[2] * inv; o0.w = v[3] * inv;
    o1.x = v[4] * inv; o1.y = v[5] * inv; o1.z = v[6] * inv; o1.w = v[7] * inv;
    o[0] = o0; o[1] = o1;
}

// ---------------------------------------------------------------------------
extern "C" void kernel_launch(void* const* d_in, const int* in_sizes, int n_in,
                              void* d_out, int out_size)
{
    const float* x  = (const float*)d_in[0];
    const float* W1 = (const float*)d_in[1];
    const float* b1 = (const float*)d_in[2];
    const float* W2 = (const float*)d_in[3];
    const float* b2 = (const float*)d_in[4];
    const float* W3 = (const float*)d_in[5];
    const float* b3 = (const float*)d_in[6];
    float* out = (float*)d_out;

    int prep_blocks = PAD_BLOCKS + (PREP_ITEMS + 255) / 256;
    prep_all_k<<<prep_blocks, 256>>>(x, W1, W2);

    cudaFuncSetAttribute(main_k, cudaFuncAttributeMaxDynamicSharedMemorySize,
                         SMEM_BYTES);
    main_k<<<NPIX / 128, 128, SMEM_BYTES>>>(b1, b2, b3, W3, out);
}